// round 15
// baseline (speedup 1.0000x reference)
#include <cuda_runtime.h>
#include <cuda_fp16.h>
#include <math.h>
#include <stdint.h>

// Problem constants
#define B_    128
#define C_    2048
#define S_    196
#define T_    20
#define HID_  1024
#define NOUT  2048               // merged hop GEMM output width
#define M_TOT (B_ * S_)          // 25088 = 98 tiles of 256

// Scratch (device globals; no allocations allowed)
__device__ __half g_vt [M_TOT * C_];     // transposed v_i, fp16 [m, c]
__device__ __half g_vih[M_TOT * HID_];   // vi fp16
__device__ __half g_et [M_TOT * NOUT];   // [e0 | t1] fp16
__device__ __half g_wl1[HID_ * C_];      // fp16 weights
__device__ __half g_w01[NOUT * HID_];    // [w_vi0 ; w_vi1] fp16
__device__ float  g_u  [B_ * HID_];
__device__ float  g_q  [B_ * HID_];      // q0
__device__ float  g_q1 [B_ * HID_];      // q1
__device__ float  g_u2 [B_ * HID_];

// ---------------------------------------------------------------------------
__device__ __forceinline__ uint32_t smem_u32(const void* p) {
    uint32_t a;
    asm("{ .reg .u64 t; cvta.to.shared.u64 t, %1; cvt.u32.u64 %0, t; }" : "=r"(a) : "l"(p));
    return a;
}
__device__ __forceinline__ float tanha(float x) {
    float y;
    asm("tanh.approx.f32 %0, %1;" : "=f"(y) : "f"(x));
    return y;
}
__device__ __forceinline__ void cpa16(uint32_t dst, const void* src) {
    asm volatile("cp.async.cg.shared.global [%0], [%1], 16;" :: "r"(dst), "l"(src));
}
__device__ __forceinline__ void ldsm_x4(uint32_t r[4], uint32_t addr) {
    asm volatile("ldmatrix.sync.aligned.m8n8.x4.shared.b16 {%0,%1,%2,%3}, [%4];"
                 : "=r"(r[0]), "=r"(r[1]), "=r"(r[2]), "=r"(r[3]) : "r"(addr));
}
__device__ __forceinline__ void mma_f16(float c[4], const uint32_t a[4],
                                        uint32_t b0, uint32_t b1) {
    asm volatile(
        "mma.sync.aligned.m16n8k16.row.col.f32.f16.f16.f32 "
        "{%0,%1,%2,%3}, {%4,%5,%6,%7}, {%8,%9}, {%0,%1,%2,%3};"
        : "+f"(c[0]), "+f"(c[1]), "+f"(c[2]), "+f"(c[3])
        : "r"(a[0]), "r"(a[1]), "r"(a[2]), "r"(a[3]), "r"(b0), "r"(b1));
}

// ---------------------------------------------------------------------------
// K1: u[b,h] = mean_t v_q[b,t,h]
// ---------------------------------------------------------------------------
__global__ __launch_bounds__(256) void mean_kernel(const float* __restrict__ vq,
                                                   float* __restrict__ u) {
    int idx = blockIdx.x * 256 + threadIdx.x;
    if (idx >= B_ * HID_) return;
    int b = idx >> 10;
    int h = idx & (HID_ - 1);
    const float* p = vq + (size_t)b * T_ * HID_ + h;
    float s = 0.f;
#pragma unroll
    for (int t = 0; t < T_; t++) s += p[(size_t)t * HID_];
    u[idx] = s * (1.0f / T_);
}

// ---------------------------------------------------------------------------
// fused fp32 -> fp16 convert of all three weight blobs
// seg0: l1_w (HID_*C_), seg1: w_vi0 (HID_*HID_), seg2: w_vi1 (HID_*HID_)
// ---------------------------------------------------------------------------
__global__ __launch_bounds__(256) void cvt3_kernel(const float* __restrict__ w0,
                                                   const float* __restrict__ w1,
                                                   const float* __restrict__ w2,
                                                   __half* __restrict__ o0,
                                                   __half* __restrict__ o1,
                                                   __half* __restrict__ o2) {
    const int N0 = HID_ * C_ / 4, N1 = HID_ * HID_ / 4;
    int i = blockIdx.x * 256 + threadIdx.x;
    const float* in;
    __half* out;
    int j = i;
    if (j < N0) { in = w0; out = o0; }
    else if (j < N0 + N1) { j -= N0; in = w1; out = o1; }
    else if (j < N0 + 2 * N1) { j -= N0 + N1; in = w2; out = o2; }
    else return;
    float4 v = *(const float4*)(in + (size_t)j * 4);
    __half2* o = (__half2*)(out + (size_t)j * 4);
    o[0] = __floats2half2_rn(v.x, v.y);
    o[1] = __floats2half2_rn(v.z, v.w);
}

// ---------------------------------------------------------------------------
// transpose v_i [b, c, s] fp32 -> vt [b*S + s, c] fp16
// ---------------------------------------------------------------------------
__global__ __launch_bounds__(256) void transpose_kernel(const float* __restrict__ vin,
                                                        __half* __restrict__ vt) {
    __shared__ float tile[32][33];
    const int c0 = blockIdx.x * 32;
    const int s0 = blockIdx.y * 32;
    const int b  = blockIdx.z;
    const int tx = threadIdx.x, ty = threadIdx.y;   // (32, 8)

#pragma unroll
    for (int i = 0; i < 4; i++) {
        int c = c0 + ty + i * 8;
        int s = s0 + tx;
        if (s < S_) tile[ty + i * 8][tx] = vin[((size_t)b * C_ + c) * S_ + s];
    }
    __syncthreads();
#pragma unroll
    for (int i = 0; i < 4; i++) {
        int s = s0 + ty + i * 8;
        int c = c0 + tx;
        if (s < S_)
            vt[((size_t)(b * S_ + s)) * C_ + c] = __float2half(tile[tx][ty + i * 8]);
    }
}

// ---------------------------------------------------------------------------
// fp16 tensor GEMM, CTA 256x128, BK=32, 8 warps (4x2), warp tile 64x64,
// 3-stage cp.async pipeline, dynamic smem, 256 threads.
//   MODE 0: epi = tanh(x + bias[n])   -> out16 (vi fp16)
//   MODE 1: global col n < HID_ : store fp16 exp(tanh(x + q0[b,n]))
//           global col n >= HID_: store fp16 raw x  (= t1)
// ---------------------------------------------------------------------------
#define RSTRIDE 80
#define TILEA_B (256 * RSTRIDE)     // 20480
#define TILEB_B (128 * RSTRIDE)     // 10240
#define SMEM_GEMM (3 * (TILEA_B + TILEB_B))   // 92160

template<int K_DIM, int MODE>
__global__ __launch_bounds__(256, 1) void mma_gemm(const __half* __restrict__ A,
                                                   const __half* __restrict__ Wt,
                                                   const float* __restrict__ bq,
                                                   __half* __restrict__ out16,
                                                   int ldo) {
    extern __shared__ __align__(16) char dynsm[];
    char* smA = dynsm;                      // 3 * TILEA_B
    char* smB = dynsm + 3 * TILEA_B;        // 3 * TILEB_B

    const int tid  = threadIdx.x;
    const int lane = tid & 31;
    const int warp = tid >> 5;           // 0..7
    const int wm   = warp >> 1;          // 0..3
    const int wn   = warp & 1;           // 0..1
    const int gid  = lane >> 2;          // 0..7
    const int tig  = lane & 3;           // 0..3
    const int quad = lane >> 3;          // 0..3
    const int r8   = lane & 7;           // 0..7

    const int n0 = blockIdx.x * 128;
    const int m0 = blockIdx.y * 256;

    const uint32_t sa  = smem_u32(smA);
    const uint32_t sbm = smem_u32(smB);

    // cp.async mapping: 256 threads; A: 4 passes of 64 rows; B: 2 passes
    const int crow = tid >> 2;           // 0..63
    const int cu   = tid & 3;            // 16B unit
    const __half* aBase = A  + (size_t)(m0 + crow) * K_DIM + cu * 8;
    const __half* bBase = Wt + (size_t)(n0 + crow) * K_DIM + cu * 8;
    const uint32_t dA = sa  + crow * RSTRIDE + cu * 16;
    const uint32_t dB = sbm + crow * RSTRIDE + cu * 16;

    auto tileLoad = [&](int k0, int buf) {
#pragma unroll
        for (int p = 0; p < 4; p++)
            cpa16(dA + buf * TILEA_B + p * 64 * RSTRIDE,
                  aBase + (size_t)p * 64 * K_DIM + k0);
#pragma unroll
        for (int p = 0; p < 2; p++)
            cpa16(dB + buf * TILEB_B + p * 64 * RSTRIDE,
                  bBase + (size_t)p * 64 * K_DIM + k0);
        asm volatile("cp.async.commit_group;");
    };

    uint32_t offA[4], offB[4];
#pragma unroll
    for (int mt = 0; mt < 4; mt++) {
        int row = wm * 64 + mt * 16 + (quad & 1) * 8 + r8;
        offA[mt] = row * RSTRIDE + (quad >> 1) * 16;
    }
#pragma unroll
    for (int p = 0; p < 4; p++) {
        int row = wn * 64 + p * 16 + (quad >> 1) * 8 + r8;
        offB[p] = row * RSTRIDE + (quad & 1) * 16;
    }

    float acc[4][8][4] = {};
    constexpr int NT = K_DIM / 32;

    tileLoad(0, 0);
    tileLoad(32, 1);
    asm volatile("cp.async.wait_group 1;");
    __syncthreads();

    int bufN = 2;
    for (int t = 0; t < NT; t++) {
        const int j = t - (t / 3) * 3;   // t % 3
        if (t + 2 < NT) {
            tileLoad((t + 2) * 32, bufN);
            bufN = (bufN == 2) ? 0 : bufN + 1;
        }

        const uint32_t baA = sa + j * TILEA_B;
        const uint32_t baB = sbm + j * TILEB_B;
#pragma unroll
        for (int ks = 0; ks < 2; ks++) {
            uint32_t a[4][4], b[4][4];
#pragma unroll
            for (int mt = 0; mt < 4; mt++) ldsm_x4(a[mt], baA + offA[mt] + ks * 32);
#pragma unroll
            for (int p = 0; p < 4; p++)   ldsm_x4(b[p],  baB + offB[p] + ks * 32);
#pragma unroll
            for (int mt = 0; mt < 4; mt++)
#pragma unroll
                for (int nt = 0; nt < 8; nt++)
                    mma_f16(acc[mt][nt], a[mt],
                            b[nt >> 1][(nt & 1) * 2], b[nt >> 1][(nt & 1) * 2 + 1]);
        }

        if (t + 2 < NT)      { asm volatile("cp.async.wait_group 1;"); }
        else if (t + 1 < NT) { asm volatile("cp.async.wait_group 0;"); }
        __syncthreads();
    }

    // ---- epilogue ----
    if (MODE == 0) {
#pragma unroll
        for (int mt = 0; mt < 4; mt++) {
#pragma unroll
            for (int h = 0; h < 2; h++) {
                int m = m0 + wm * 64 + mt * 16 + gid + h * 8;
#pragma unroll
                for (int nt = 0; nt < 8; nt++) {
                    int n = n0 + wn * 64 + nt * 8 + tig * 2;
                    float r0 = tanha(acc[mt][nt][h * 2]     + bq[n]);
                    float r1 = tanha(acc[mt][nt][h * 2 + 1] + bq[n + 1]);
                    *(__half2*)(out16 + (size_t)m * ldo + n) = __floats2half2_rn(r0, r1);
                }
            }
        }
    } else {
        const bool hop0 = (n0 < HID_);   // uniform per CTA
#pragma unroll
        for (int mt = 0; mt < 4; mt++) {
#pragma unroll
            for (int h = 0; h < 2; h++) {
                int m = m0 + wm * 64 + mt * 16 + gid + h * 8;
                const float* qrow = bq + (size_t)(m / S_) * HID_;
#pragma unroll
                for (int nt = 0; nt < 8; nt++) {
                    int n = n0 + wn * 64 + nt * 8 + tig * 2;
                    float x0 = acc[mt][nt][h * 2];
                    float x1 = acc[mt][nt][h * 2 + 1];
                    __half2 o;
                    if (hop0) {
                        o = __floats2half2_rn(__expf(tanha(x0 + qrow[n])),
                                              __expf(tanha(x1 + qrow[n + 1])));
                    } else {
                        o = __floats2half2_rn(x0, x1);
                    }
                    *(__half2*)(out16 + (size_t)m * ldo + n) = o;
                }
            }
        }
    }
}

// ---------------------------------------------------------------------------
// K3: q[b,k] = sum_h u[b,h] * w_u[k,h] + b_u[k]   (tiny: 128x1024x1024, fp32)
// ---------------------------------------------------------------------------
__global__ __launch_bounds__(256) void gemmq_kernel(const float* __restrict__ u,
                                                    const float* __restrict__ w,
                                                    const float* __restrict__ bias,
                                                    float* __restrict__ out) {
    __shared__ float As[16][64];
    __shared__ float Bs[16][68];

    const int m0 = blockIdx.x * 64;
    const int n0 = blockIdx.y * 64;
    const int tid = threadIdx.x;
    const int tx = tid & 15, ty = tid >> 4;
    const int lm = tid & 63;
    const int lcA = tid >> 6;
    const int lcB = tid & 15;
    const int lnB = tid >> 4;

    float acc[4][4] = {};

    for (int c0 = 0; c0 < HID_; c0 += 16) {
#pragma unroll
        for (int i = 0; i < 4; i++) {
            int c = lcA + i * 4;
            As[c][lm] = u[(size_t)(m0 + lm) * HID_ + c0 + c];
        }
#pragma unroll
        for (int i = 0; i < 4; i++) {
            int n = lnB + i * 16;
            Bs[lcB][n] = w[(size_t)(n0 + n) * HID_ + c0 + lcB];
        }
        __syncthreads();
#pragma unroll
        for (int kk = 0; kk < 16; kk++) {
            float4 av = *(const float4*)&As[kk][ty * 4];
            float4 bv = *(const float4*)&Bs[kk][tx * 4];
            float a_[4] = {av.x, av.y, av.z, av.w};
            float b_[4] = {bv.x, bv.y, bv.z, bv.w};
#pragma unroll
            for (int i = 0; i < 4; i++)
#pragma unroll
                for (int j = 0; j < 4; j++) acc[i][j] += a_[i] * b_[j];
        }
        __syncthreads();
    }

#pragma unroll
    for (int i = 0; i < 4; i++) {
        float* orow = out + (size_t)(m0 + ty * 4 + i) * HID_ + n0 + tx * 4;
#pragma unroll
        for (int j = 0; j < 4; j++)
            orow[j] = acc[i][j] + bias[n0 + tx * 4 + j];
    }
}

// ---------------------------------------------------------------------------
// hop reduce + finalize: per (b,n):
//   MODE 0: e = et[.., n]           (already exponentiated)
//   MODE 1: e = exp(tanh(et[.., HID_+n] + q1[b,n]))
//   uout[b,n] = uin[b,n] + (sum_s e*vi) / (sum_s e)    (vi fp16)
// ---------------------------------------------------------------------------
template<int MODE>
__global__ __launch_bounds__(256) void hop_reduce(const __half* __restrict__ et,
                                                  const float* __restrict__ q1,
                                                  const __half* __restrict__ vih,
                                                  const float* __restrict__ uin,
                                                  float* __restrict__ uout) {
    int b = blockIdx.x;
    int n = blockIdx.y * 256 + threadIdx.x;
    const __half* ep = et  + (size_t)b * S_ * NOUT + (MODE ? HID_ : 0) + n;
    const __half* vp = vih + (size_t)b * S_ * HID_ + n;
    float qv = MODE ? q1[(size_t)b * HID_ + n] : 0.f;
    float E = 0.f, W = 0.f;
#pragma unroll 4
    for (int s = 0; s < S_; s++) {
        float tv = __half2float(ep[(size_t)s * NOUT]);
        float e = MODE ? __expf(tanha(tv + qv)) : tv;
        E += e;
        W += e * __half2float(vp[(size_t)s * HID_]);
    }
    size_t idx = (size_t)b * HID_ + n;
    uout[idx] = uin[idx] + W / E;
}

// ---------------------------------------------------------------------------
extern "C" void kernel_launch(void* const* d_in, const int* in_sizes, int n_in,
                              void* d_out, int out_size) {
    const float* v_i   = (const float*)d_in[0];
    const float* v_q   = (const float*)d_in[1];
    const float* l1_w  = (const float*)d_in[2];
    const float* l1_b  = (const float*)d_in[3];
    const float* w_vi0 = (const float*)d_in[4];
    const float* w_u0  = (const float*)d_in[5];
    const float* b_u0  = (const float*)d_in[6];
    const float* w_vi1 = (const float*)d_in[7];
    const float* w_u1  = (const float*)d_in[8];
    const float* b_u1  = (const float*)d_in[9];
    float* out = (float*)d_out;

    __half *vt_p, *vih_p, *wl1_p, *w01_p, *et_p;
    float *u_p, *q_p, *q1_p, *u2_p;
    cudaGetSymbolAddress((void**)&vt_p,  g_vt);
    cudaGetSymbolAddress((void**)&vih_p, g_vih);
    cudaGetSymbolAddress((void**)&wl1_p, g_wl1);
    cudaGetSymbolAddress((void**)&w01_p, g_w01);
    cudaGetSymbolAddress((void**)&et_p,  g_et);
    cudaGetSymbolAddress((void**)&u_p,   g_u);
    cudaGetSymbolAddress((void**)&q_p,   g_q);
    cudaGetSymbolAddress((void**)&q1_p,  g_q1);
    cudaGetSymbolAddress((void**)&u2_p,  g_u2);

    cudaFuncSetAttribute(mma_gemm<C_, 0>,
                         cudaFuncAttributeMaxDynamicSharedMemorySize, SMEM_GEMM);
    cudaFuncSetAttribute(mma_gemm<HID_, 1>,
                         cudaFuncAttributeMaxDynamicSharedMemorySize, SMEM_GEMM);

    const int NBH = (B_ * HID_ + 255) / 256;
    const int NCVT = (HID_ * C_ / 4) + 2 * (HID_ * HID_ / 4);

    // prologue
    mean_kernel<<<NBH, 256>>>(v_q, u_p);
    cvt3_kernel<<<(NCVT + 255) / 256, 256>>>(l1_w, w_vi0, w_vi1,
                                             wl1_p, w01_p, w01_p + (size_t)HID_ * HID_);
    transpose_kernel<<<dim3(C_ / 32, 7, B_), dim3(32, 8)>>>(v_i, vt_p);

    // q0 = u0 @ w_u0^T + b_u0
    gemmq_kernel<<<dim3(2, 16), 256>>>(u_p, w_u0, b_u0, q_p);

    // vi = tanh(l1(v_i))  (fp16)
    mma_gemm<C_, 0><<<dim3(8, 98), 256, SMEM_GEMM>>>(vt_p, wl1_p, l1_b, vih_p, HID_);

    // merged hop GEMM: [e0 | t1] = vi @ [w_vi0 ; w_vi1]^T
    mma_gemm<HID_, 1><<<dim3(16, 98), 256, SMEM_GEMM>>>(vih_p, w01_p, q_p, et_p, NOUT);

    // hop 0 reduce -> u2
    hop_reduce<0><<<dim3(B_, 4), 256>>>(et_p, nullptr, vih_p, u_p, u2_p);

    // hop 1
    gemmq_kernel<<<dim3(2, 16), 256>>>(u2_p, w_u1, b_u1, q1_p);
    hop_reduce<1><<<dim3(B_, 4), 256>>>(et_p, q1_p, vih_p, u2_p, out);
}

// round 17
// speedup vs baseline: 1.4081x; 1.4081x over previous
#include <cuda_runtime.h>
#include <cuda_fp16.h>
#include <math.h>
#include <stdint.h>

// Problem constants
#define B_    128
#define C_    2048
#define S_    196
#define T_    20
#define HID_  1024
#define NOUT  2048               // merged hop GEMM output width
#define M_TOT (B_ * S_)          // 25088 = 196 tiles of 128

// Scratch (device globals; no allocations allowed)
__device__ __half g_vt [M_TOT * C_];     // transposed v_i, fp16 [m, c]
__device__ __half g_vih[M_TOT * HID_];   // vi fp16
__device__ __half g_et [M_TOT * NOUT];   // [e0 | t1] fp16
__device__ __half g_wl1[HID_ * C_];      // fp16 weights
__device__ __half g_w01[NOUT * HID_];    // [w_vi0 ; w_vi1] fp16
__device__ float  g_u  [B_ * HID_];
__device__ float  g_q  [B_ * HID_];      // q0
__device__ float  g_q1 [B_ * HID_];      // q1
__device__ float  g_u2 [B_ * HID_];

// ---------------------------------------------------------------------------
__device__ __forceinline__ uint32_t smem_u32(const void* p) {
    uint32_t a;
    asm("{ .reg .u64 t; cvta.to.shared.u64 t, %1; cvt.u32.u64 %0, t; }" : "=r"(a) : "l"(p));
    return a;
}
__device__ __forceinline__ float tanha(float x) {
    float y;
    asm("tanh.approx.f32 %0, %1;" : "=f"(y) : "f"(x));
    return y;
}
__device__ __forceinline__ void cpa16(uint32_t dst, const void* src) {
    asm volatile("cp.async.cg.shared.global [%0], [%1], 16;" :: "r"(dst), "l"(src));
}
__device__ __forceinline__ void ldsm_x4(uint32_t r[4], uint32_t addr) {
    asm volatile("ldmatrix.sync.aligned.m8n8.x4.shared.b16 {%0,%1,%2,%3}, [%4];"
                 : "=r"(r[0]), "=r"(r[1]), "=r"(r[2]), "=r"(r[3]) : "r"(addr));
}
__device__ __forceinline__ void mma_f16(float c[4], const uint32_t a[4],
                                        uint32_t b0, uint32_t b1) {
    asm volatile(
        "mma.sync.aligned.m16n8k16.row.col.f32.f16.f16.f32 "
        "{%0,%1,%2,%3}, {%4,%5,%6,%7}, {%8,%9}, {%0,%1,%2,%3};"
        : "+f"(c[0]), "+f"(c[1]), "+f"(c[2]), "+f"(c[3])
        : "r"(a[0]), "r"(a[1]), "r"(a[2]), "r"(a[3]), "r"(b0), "r"(b1));
}

// ---------------------------------------------------------------------------
// K1: u[b,h] = mean_t v_q[b,t,h]
// ---------------------------------------------------------------------------
__global__ __launch_bounds__(256) void mean_kernel(const float* __restrict__ vq,
                                                   float* __restrict__ u) {
    int idx = blockIdx.x * 256 + threadIdx.x;
    if (idx >= B_ * HID_) return;
    int b = idx >> 10;
    int h = idx & (HID_ - 1);
    const float* p = vq + (size_t)b * T_ * HID_ + h;
    float s = 0.f;
#pragma unroll
    for (int t = 0; t < T_; t++) s += p[(size_t)t * HID_];
    u[idx] = s * (1.0f / T_);
}

// ---------------------------------------------------------------------------
// init q buffers with bias (for split-K atomic accumulation)
// ---------------------------------------------------------------------------
__global__ __launch_bounds__(256) void initq_kernel(float* __restrict__ q0,
                                                    const float* __restrict__ b0,
                                                    float* __restrict__ q1,
                                                    const float* __restrict__ b1) {
    int i = blockIdx.x * 256 + threadIdx.x;
    if (i >= B_ * HID_) return;
    int n = i & (HID_ - 1);
    q0[i] = b0[n];
    q1[i] = b1[n];
}

// ---------------------------------------------------------------------------
// fused fp32 -> fp16 convert of all three weight blobs
// ---------------------------------------------------------------------------
__global__ __launch_bounds__(256) void cvt3_kernel(const float* __restrict__ w0,
                                                   const float* __restrict__ w1,
                                                   const float* __restrict__ w2,
                                                   __half* __restrict__ o0,
                                                   __half* __restrict__ o1,
                                                   __half* __restrict__ o2) {
    const int N0 = HID_ * C_ / 4, N1 = HID_ * HID_ / 4;
    int i = blockIdx.x * 256 + threadIdx.x;
    const float* in;
    __half* out;
    int j = i;
    if (j < N0) { in = w0; out = o0; }
    else if (j < N0 + N1) { j -= N0; in = w1; out = o1; }
    else if (j < N0 + 2 * N1) { j -= N0 + N1; in = w2; out = o2; }
    else return;
    float4 v = *(const float4*)(in + (size_t)j * 4);
    __half2* o = (__half2*)(out + (size_t)j * 4);
    o[0] = __floats2half2_rn(v.x, v.y);
    o[1] = __floats2half2_rn(v.z, v.w);
}

// ---------------------------------------------------------------------------
// transpose v_i [b, c, s] fp32 -> vt [b*S + s, c] fp16
// ---------------------------------------------------------------------------
__global__ __launch_bounds__(256) void transpose_kernel(const float* __restrict__ vin,
                                                        __half* __restrict__ vt) {
    __shared__ float tile[32][33];
    const int c0 = blockIdx.x * 32;
    const int s0 = blockIdx.y * 32;
    const int b  = blockIdx.z;
    const int tx = threadIdx.x, ty = threadIdx.y;   // (32, 8)

#pragma unroll
    for (int i = 0; i < 4; i++) {
        int c = c0 + ty + i * 8;
        int s = s0 + tx;
        if (s < S_) tile[ty + i * 8][tx] = vin[((size_t)b * C_ + c) * S_ + s];
    }
    __syncthreads();
#pragma unroll
    for (int i = 0; i < 4; i++) {
        int s = s0 + ty + i * 8;
        int c = c0 + tx;
        if (s < S_)
            vt[((size_t)(b * S_ + s)) * C_ + c] = __float2half(tile[tx][ty + i * 8]);
    }
}

// ---------------------------------------------------------------------------
// fp16 tensor GEMM, CTA 128x128, BK=32, 4 warps (2x2), warp tile 64x64,
// 3-stage cp.async pipeline, dynamic smem, 128 threads.  (R13 geometry)
//   MODE 0: epi = tanh(x + bias[n])   -> out16 (vi fp16)
//   MODE 1: global col n < HID_ : store fp16 exp(tanh(x + q0[b,n]))
//           global col n >= HID_: store fp16 raw x  (= t1)
// ---------------------------------------------------------------------------
#define RSTRIDE 80
#define TILEB  (128 * RSTRIDE)
#define SMEM_GEMM (6 * TILEB)      // 3 stages x (A + B)

template<int K_DIM, int MODE>
__global__ __launch_bounds__(128, 2) void mma_gemm(const __half* __restrict__ A,
                                                   const __half* __restrict__ Wt,
                                                   const float* __restrict__ bq,
                                                   __half* __restrict__ out16,
                                                   int ldo) {
    extern __shared__ __align__(16) char dynsm[];
    char* smA = dynsm;                  // 3 * TILEB
    char* smB = dynsm + 3 * TILEB;      // 3 * TILEB

    const int tid  = threadIdx.x;
    const int lane = tid & 31;
    const int warp = tid >> 5;           // 0..3
    const int wm   = warp >> 1;          // 0..1
    const int wn   = warp & 1;           // 0..1
    const int gid  = lane >> 2;          // 0..7
    const int tig  = lane & 3;           // 0..3
    const int quad = lane >> 3;          // 0..3
    const int r8   = lane & 7;           // 0..7

    const int n0 = blockIdx.x * 128;
    const int m0 = blockIdx.y * 128;

    const uint32_t sa  = smem_u32(smA);
    const uint32_t sbm = smem_u32(smB);

    // cp.async mapping: 128 threads, 4 passes of 32 rows
    const int crow = tid >> 2;           // 0..31
    const int cu   = tid & 3;            // 16B unit
    const __half* aBase = A  + (size_t)(m0 + crow) * K_DIM + cu * 8;
    const __half* bBase = Wt + (size_t)(n0 + crow) * K_DIM + cu * 8;
    const uint32_t dA = sa  + crow * RSTRIDE + cu * 16;
    const uint32_t dB = sbm + crow * RSTRIDE + cu * 16;

    auto tileLoad = [&](int k0, int buf) {
#pragma unroll
        for (int p = 0; p < 4; p++) {
            cpa16(dA + buf * TILEB + p * 32 * RSTRIDE,
                  aBase + (size_t)p * 32 * K_DIM + k0);
            cpa16(dB + buf * TILEB + p * 32 * RSTRIDE,
                  bBase + (size_t)p * 32 * K_DIM + k0);
        }
        asm volatile("cp.async.commit_group;");
    };

    uint32_t offA[4], offB[4];
#pragma unroll
    for (int mt = 0; mt < 4; mt++) {
        int row = wm * 64 + mt * 16 + (quad & 1) * 8 + r8;
        offA[mt] = row * RSTRIDE + (quad >> 1) * 16;
    }
#pragma unroll
    for (int p = 0; p < 4; p++) {
        int row = wn * 64 + p * 16 + (quad >> 1) * 8 + r8;
        offB[p] = row * RSTRIDE + (quad & 1) * 16;
    }

    float acc[4][8][4] = {};
    constexpr int NT = K_DIM / 32;

    tileLoad(0, 0);
    tileLoad(32, 1);
    asm volatile("cp.async.wait_group 1;");
    __syncthreads();

    int bufN = 2;
    for (int t = 0; t < NT; t++) {
        const int j = t - (t / 3) * 3;   // t % 3
        if (t + 2 < NT) {
            tileLoad((t + 2) * 32, bufN);
            bufN = (bufN == 2) ? 0 : bufN + 1;
        }

        const uint32_t baA = sa + j * TILEB;
        const uint32_t baB = sbm + j * TILEB;
#pragma unroll
        for (int ks = 0; ks < 2; ks++) {
            uint32_t a[4][4], b[4][4];
#pragma unroll
            for (int mt = 0; mt < 4; mt++) ldsm_x4(a[mt], baA + offA[mt] + ks * 32);
#pragma unroll
            for (int p = 0; p < 4; p++)   ldsm_x4(b[p],  baB + offB[p] + ks * 32);
#pragma unroll
            for (int mt = 0; mt < 4; mt++)
#pragma unroll
                for (int nt = 0; nt < 8; nt++)
                    mma_f16(acc[mt][nt], a[mt],
                            b[nt >> 1][(nt & 1) * 2], b[nt >> 1][(nt & 1) * 2 + 1]);
        }

        if (t + 2 < NT)      { asm volatile("cp.async.wait_group 1;"); }
        else if (t + 1 < NT) { asm volatile("cp.async.wait_group 0;"); }
        __syncthreads();
    }

    // ---- epilogue ----
    if (MODE == 0) {
#pragma unroll
        for (int mt = 0; mt < 4; mt++) {
#pragma unroll
            for (int h = 0; h < 2; h++) {
                int m = m0 + wm * 64 + mt * 16 + gid + h * 8;
#pragma unroll
                for (int nt = 0; nt < 8; nt++) {
                    int n = n0 + wn * 64 + nt * 8 + tig * 2;
                    float r0 = tanha(acc[mt][nt][h * 2]     + bq[n]);
                    float r1 = tanha(acc[mt][nt][h * 2 + 1] + bq[n + 1]);
                    *(__half2*)(out16 + (size_t)m * ldo + n) = __floats2half2_rn(r0, r1);
                }
            }
        }
    } else {
        const bool hop0 = (n0 < HID_);   // uniform per CTA
#pragma unroll
        for (int mt = 0; mt < 4; mt++) {
#pragma unroll
            for (int h = 0; h < 2; h++) {
                int m = m0 + wm * 64 + mt * 16 + gid + h * 8;
                const float* qrow = bq + (size_t)(m / S_) * HID_;
#pragma unroll
                for (int nt = 0; nt < 8; nt++) {
                    int n = n0 + wn * 64 + nt * 8 + tig * 2;
                    float x0 = acc[mt][nt][h * 2];
                    float x1 = acc[mt][nt][h * 2 + 1];
                    __half2 o;
                    if (hop0) {
                        o = __floats2half2_rn(__expf(tanha(x0 + qrow[n])),
                                              __expf(tanha(x1 + qrow[n + 1])));
                    } else {
                        o = __floats2half2_rn(x0, x1);
                    }
                    *(__half2*)(out16 + (size_t)m * ldo + n) = o;
                }
            }
        }
    }
}

// ---------------------------------------------------------------------------
// K3: split-K gemmq:  q[b,k] += sum_{h in slice} u[b,h] * w_u[k,h]
// grid (2, 16, KS=8): 64x64 tile over K-slice of 128. Output pre-init'd with
// bias. fp32 SIMT (accuracy on the q path), atomicAdd combine.
// ---------------------------------------------------------------------------
#define KSLICE 128

__global__ __launch_bounds__(256) void gemmq_kernel(const float* __restrict__ u,
                                                    const float* __restrict__ w,
                                                    float* __restrict__ out) {
    __shared__ float As[16][64];
    __shared__ float Bs[16][68];

    const int m0 = blockIdx.x * 64;
    const int n0 = blockIdx.y * 64;
    const int k0base = blockIdx.z * KSLICE;
    const int tid = threadIdx.x;
    const int tx = tid & 15, ty = tid >> 4;
    const int lm = tid & 63;
    const int lcA = tid >> 6;
    const int lcB = tid & 15;
    const int lnB = tid >> 4;

    float acc[4][4] = {};

    for (int c0 = k0base; c0 < k0base + KSLICE; c0 += 16) {
#pragma unroll
        for (int i = 0; i < 4; i++) {
            int c = lcA + i * 4;
            As[c][lm] = u[(size_t)(m0 + lm) * HID_ + c0 + c];
        }
#pragma unroll
        for (int i = 0; i < 4; i++) {
            int n = lnB + i * 16;
            Bs[lcB][n] = w[(size_t)(n0 + n) * HID_ + c0 + lcB];
        }
        __syncthreads();
#pragma unroll
        for (int kk = 0; kk < 16; kk++) {
            float4 av = *(const float4*)&As[kk][ty * 4];
            float4 bv = *(const float4*)&Bs[kk][tx * 4];
            float a_[4] = {av.x, av.y, av.z, av.w};
            float b_[4] = {bv.x, bv.y, bv.z, bv.w};
#pragma unroll
            for (int i = 0; i < 4; i++)
#pragma unroll
                for (int j = 0; j < 4; j++) acc[i][j] += a_[i] * b_[j];
        }
        __syncthreads();
    }

#pragma unroll
    for (int i = 0; i < 4; i++) {
        float* orow = out + (size_t)(m0 + ty * 4 + i) * HID_ + n0 + tx * 4;
#pragma unroll
        for (int j = 0; j < 4; j++)
            atomicAdd(&orow[j], acc[i][j]);
    }
}

// ---------------------------------------------------------------------------
// hop reduce + finalize: per (b,n):
//   MODE 0: e = et[.., n]           (already exponentiated)
//   MODE 1: e = exp(tanh(et[.., HID_+n] + q1[b,n]))
//   uout[b,n] = uin[b,n] + (sum_s e*vi) / (sum_s e)    (vi fp16)
// ---------------------------------------------------------------------------
template<int MODE>
__global__ __launch_bounds__(256) void hop_reduce(const __half* __restrict__ et,
                                                  const float* __restrict__ q1,
                                                  const __half* __restrict__ vih,
                                                  const float* __restrict__ uin,
                                                  float* __restrict__ uout) {
    int b = blockIdx.x;
    int n = blockIdx.y * 256 + threadIdx.x;
    const __half* ep = et  + (size_t)b * S_ * NOUT + (MODE ? HID_ : 0) + n;
    const __half* vp = vih + (size_t)b * S_ * HID_ + n;
    float qv = MODE ? q1[(size_t)b * HID_ + n] : 0.f;
    float E = 0.f, W = 0.f;
#pragma unroll 4
    for (int s = 0; s < S_; s++) {
        float tv = __half2float(ep[(size_t)s * NOUT]);
        float e = MODE ? __expf(tanha(tv + qv)) : tv;
        E += e;
        W += e * __half2float(vp[(size_t)s * HID_]);
    }
    size_t idx = (size_t)b * HID_ + n;
    uout[idx] = uin[idx] + W / E;
}

// ---------------------------------------------------------------------------
extern "C" void kernel_launch(void* const* d_in, const int* in_sizes, int n_in,
                              void* d_out, int out_size) {
    const float* v_i   = (const float*)d_in[0];
    const float* v_q   = (const float*)d_in[1];
    const float* l1_w  = (const float*)d_in[2];
    const float* l1_b  = (const float*)d_in[3];
    const float* w_vi0 = (const float*)d_in[4];
    const float* w_u0  = (const float*)d_in[5];
    const float* b_u0  = (const float*)d_in[6];
    const float* w_vi1 = (const float*)d_in[7];
    const float* w_u1  = (const float*)d_in[8];
    const float* b_u1  = (const float*)d_in[9];
    float* out = (float*)d_out;

    __half *vt_p, *vih_p, *wl1_p, *w01_p, *et_p;
    float *u_p, *q_p, *q1_p, *u2_p;
    cudaGetSymbolAddress((void**)&vt_p,  g_vt);
    cudaGetSymbolAddress((void**)&vih_p, g_vih);
    cudaGetSymbolAddress((void**)&wl1_p, g_wl1);
    cudaGetSymbolAddress((void**)&w01_p, g_w01);
    cudaGetSymbolAddress((void**)&et_p,  g_et);
    cudaGetSymbolAddress((void**)&u_p,   g_u);
    cudaGetSymbolAddress((void**)&q_p,   g_q);
    cudaGetSymbolAddress((void**)&q1_p,  g_q1);
    cudaGetSymbolAddress((void**)&u2_p,  g_u2);

    cudaFuncSetAttribute(mma_gemm<C_, 0>,
                         cudaFuncAttributeMaxDynamicSharedMemorySize, SMEM_GEMM);
    cudaFuncSetAttribute(mma_gemm<HID_, 1>,
                         cudaFuncAttributeMaxDynamicSharedMemorySize, SMEM_GEMM);

    const int NBH = (B_ * HID_ + 255) / 256;
    const int NCVT = (HID_ * C_ / 4) + 2 * (HID_ * HID_ / 4);

    // prologue
    mean_kernel<<<NBH, 256>>>(v_q, u_p);
    initq_kernel<<<NBH, 256>>>(q_p, b_u0, q1_p, b_u1);
    cvt3_kernel<<<(NCVT + 255) / 256, 256>>>(l1_w, w_vi0, w_vi1,
                                             wl1_p, w01_p, w01_p + (size_t)HID_ * HID_);
    transpose_kernel<<<dim3(C_ / 32, 7, B_), dim3(32, 8)>>>(v_i, vt_p);

    // q0 += u0 @ w_u0^T   (split-K, bias pre-initialized)
    gemmq_kernel<<<dim3(2, 16, HID_ / KSLICE), 256>>>(u_p, w_u0, q_p);

    // vi = tanh(l1(v_i))  (fp16)
    mma_gemm<C_, 0><<<dim3(8, 196), 128, SMEM_GEMM>>>(vt_p, wl1_p, l1_b, vih_p, HID_);

    // merged hop GEMM: [e0 | t1] = vi @ [w_vi0 ; w_vi1]^T
    mma_gemm<HID_, 1><<<dim3(16, 196), 128, SMEM_GEMM>>>(vih_p, w01_p, q_p, et_p, NOUT);

    // hop 0 reduce -> u2
    hop_reduce<0><<<dim3(B_, 4), 256>>>(et_p, nullptr, vih_p, u_p, u2_p);

    // hop 1
    gemmq_kernel<<<dim3(2, 16, HID_ / KSLICE), 256>>>(u2_p, w_u1, q1_p);
    hop_reduce<1><<<dim3(B_, 4), 256>>>(et_p, q1_p, vih_p, u2_p, out);
}